// round 3
// baseline (speedup 1.0000x reference)
#include <cuda_runtime.h>

// ZBLRepulsion: E = sum over edges of 0.5*Zi*Zj/dr * f(dist) * cos_cutoff(dr)
// Inputs (metadata order): R[f32, n*3], Z[i32, n], idx[i32, 2*E],
//                          a_exp[f32,1], a_num[f32,1], coefficients[f32,4], exponents[f32,4]
// Output: f32 scalar.

#define MAX_ATOMS  131072
#define MAX_BLOCKS 16384
#define PACK_BLK   256
#define EDGE_BLK   256

// Packed per-atom table: {x, y, z, Zf + Zp*0.125}, Zp = Z^a_exp
__device__ float4 g_P[MAX_ATOMS];
__device__ float  g_partials[MAX_BLOCKS];

// 4 atoms per thread: 12 floats of R = exactly 3 float4 loads, Z = 1 int4 load.
__global__ void pack_kernel(const float* __restrict__ R,
                            const int* __restrict__ Z,
                            const float* __restrict__ a_exp,
                            int n_atoms) {
    int t = blockIdx.x * blockDim.x + threadIdx.x;
    int base = t * 4;
    float ae = __ldg(a_exp);

    if (base + 3 < n_atoms) {
        const float4* R4 = (const float4*)R;
        float4 r0 = R4[3 * t + 0];
        float4 r1 = R4[3 * t + 1];
        float4 r2 = R4[3 * t + 2];
        int4   zv = ((const int4*)Z)[t];

        float zf0 = (float)zv.x, zf1 = (float)zv.y;
        float zf2 = (float)zv.z, zf3 = (float)zv.w;
        float4 p0 = {r0.x, r0.y, r0.z, zf0 + 0.125f * __powf(zf0, ae)};
        float4 p1 = {r0.w, r1.x, r1.y, zf1 + 0.125f * __powf(zf1, ae)};
        float4 p2 = {r1.z, r1.w, r2.x, zf2 + 0.125f * __powf(zf2, ae)};
        float4 p3 = {r2.y, r2.z, r2.w, zf3 + 0.125f * __powf(zf3, ae)};
        g_P[base + 0] = p0;
        g_P[base + 1] = p1;
        g_P[base + 2] = p2;
        g_P[base + 3] = p3;
    } else if (base < n_atoms) {
        for (int i = base; i < n_atoms; i++) {
            float zf = (float)Z[i];
            float4 p;
            p.x = R[3 * i + 0];
            p.y = R[3 * i + 1];
            p.z = R[3 * i + 2];
            p.w = zf + 0.125f * __powf(zf, ae);
            g_P[i] = p;
        }
    }
}

// Per-edge energy. Assumes caller verified validity and r2 < 36 (cutoff > 0).
__device__ __forceinline__ float edge_energy(float4 Pi, float4 Pj,
                                             float inv_anum,
                                             const float* c, const float* e) {
    float dx = Pj.x - Pi.x, dy = Pj.y - Pi.y, dz = Pj.z - Pi.z;
    float r2 = fmaf(dx, dx, fmaf(dy, dy, dz * dz));
    float zfi = truncf(Pi.w);
    float zfj = truncf(Pj.w);
    float zpi = (Pi.w - zfi) * 8.0f;
    float zpj = (Pj.w - zfj) * 8.0f;
    float r2c = fmaxf(r2, 4.0e-4f);            // lower clip: dr >= 0.02
    float dr  = sqrtf(r2c);                    // dr <= 6 guaranteed by r2 < 36 gate
    float rinv = __fdividef(1.0f, dr);
    const float PI_OVER_6 = 0.52359877559829887308f;
    float cut = 0.5f * (__cosf(dr * PI_OVER_6) + 1.0f);
    float dist = dr * (zpi + zpj) * inv_anum;
    float f = c[0] * __expf(-e[0] * dist)
            + c[1] * __expf(-e[1] * dist)
            + c[2] * __expf(-e[2] * dist)
            + c[3] * __expf(-e[3] * dist);
    return 0.5f * zfi * zfj * rinv * f * cut;
}

// __launch_bounds__(256, 5): cap regs at 48 -> 1280 thr/SM (40 warps),
// 40 warps x 8 in-flight gathers = 320 outstanding sectors/SM, which covers
// L2 latency (234 cyc) at the per-SM LTS share (~42 B/cyc needs ~310).
__global__ void __launch_bounds__(EDGE_BLK, 5)
edge_kernel(const int* __restrict__ idx, int n_edges, int n_atoms,
            const float* __restrict__ a_num,
            const float* __restrict__ coefficients,
            const float* __restrict__ exponents) {
    const int t = blockIdx.x * blockDim.x + threadIdx.x;
    const int nvec = n_edges >> 2;   // 4 edges per thread (vectorized idx loads)

    float cc[4] = {__ldg(coefficients + 0), __ldg(coefficients + 1),
                   __ldg(coefficients + 2), __ldg(coefficients + 3)};
    float ee[4] = {__ldg(exponents + 0), __ldg(exponents + 1),
                   __ldg(exponents + 2), __ldg(exponents + 3)};
    float inv_anum = __fdividef(1.0f, __ldg(a_num));

    float acc = 0.0f;

    if (t < nvec) {
        const int4* ii4 = (const int4*)idx;
        const int4* jj4 = (const int4*)(idx + n_edges);
        int4 iv = ii4[t];
        int4 jv = jj4[t];
        int is[4] = {iv.x, iv.y, iv.z, iv.w};
        int js[4] = {jv.x, jv.y, jv.z, jv.w};

        bool  valid[4];
        float4 Pi[4], Pj[4];
        // Batch the gathers front-to-back for MLP
        #pragma unroll
        for (int k = 0; k < 4; k++) {
            valid[k] = ((unsigned)is[k] < (unsigned)n_atoms) &&
                       ((unsigned)js[k] < (unsigned)n_atoms);
            int si = valid[k] ? is[k] : 0;
            int sj = valid[k] ? js[k] : 0;
            Pi[k] = g_P[si];
            Pj[k] = g_P[sj];
        }

        #pragma unroll
        for (int k = 0; k < 4; k++) {
            float dx = Pj[k].x - Pi[k].x;
            float dy = Pj[k].y - Pi[k].y;
            float dz = Pj[k].z - Pi[k].z;
            float r2 = fmaf(dx, dx, fmaf(dy, dy, dz * dz));
            // r2 >= 36 -> dr clips to 6 -> cutoff == 0 exactly -> contribution 0.
            // Only ~0.5% of edges are inside the cutoff; most warps skip the
            // transcendental block entirely via SIMT predication.
            if (valid[k] && r2 < 36.0f) {
                acc += edge_energy(Pi[k], Pj[k], inv_anum, cc, ee);
            }
        }
    }

    // Deterministic block reduction: warp shuffle, then smem across warps.
    #pragma unroll
    for (int off = 16; off > 0; off >>= 1)
        acc += __shfl_down_sync(0xffffffffu, acc, off);

    __shared__ float warp_sums[EDGE_BLK / 32];
    int lane = threadIdx.x & 31;
    int wid  = threadIdx.x >> 5;
    if (lane == 0) warp_sums[wid] = acc;
    __syncthreads();
    if (wid == 0) {
        float v = (lane < EDGE_BLK / 32) ? warp_sums[lane] : 0.0f;
        #pragma unroll
        for (int off = 4; off > 0; off >>= 1)
            v += __shfl_down_sync(0xffffffffu, v, off);
        if (lane == 0) g_partials[blockIdx.x] = v;
    }
}

__global__ void __launch_bounds__(1024)
final_reduce_kernel(float* __restrict__ out, int n_blocks,
                    const int* __restrict__ idx, int n_edges, int n_atoms,
                    const float* __restrict__ a_num,
                    const float* __restrict__ coefficients,
                    const float* __restrict__ exponents) {
    float acc = 0.0f;
    for (int b = threadIdx.x; b < n_blocks; b += 1024)
        acc += g_partials[b];

    // Tail edges (n_edges % 4), handled by thread 0 only (fixed order).
    if (threadIdx.x == 0) {
        float cc[4] = {coefficients[0], coefficients[1], coefficients[2], coefficients[3]};
        float ee[4] = {exponents[0], exponents[1], exponents[2], exponents[3]};
        float inv_anum = __fdividef(1.0f, a_num[0]);
        int start = (n_edges >> 2) << 2;
        for (int e = start; e < n_edges; e++) {
            int i = idx[e];
            int j = idx[n_edges + e];
            if ((unsigned)i < (unsigned)n_atoms && (unsigned)j < (unsigned)n_atoms) {
                float4 Pi = g_P[i], Pj = g_P[j];
                float dx = Pj.x - Pi.x, dy = Pj.y - Pi.y, dz = Pj.z - Pi.z;
                float r2 = fmaf(dx, dx, fmaf(dy, dy, dz * dz));
                if (r2 < 36.0f) acc += edge_energy(Pi, Pj, inv_anum, cc, ee);
            }
        }
    }

    // Block reduction
    #pragma unroll
    for (int off = 16; off > 0; off >>= 1)
        acc += __shfl_down_sync(0xffffffffu, acc, off);
    __shared__ float warp_sums[32];
    int lane = threadIdx.x & 31;
    int wid  = threadIdx.x >> 5;
    if (lane == 0) warp_sums[wid] = acc;
    __syncthreads();
    if (wid == 0) {
        float v = (lane < 32) ? warp_sums[lane] : 0.0f;
        #pragma unroll
        for (int off = 16; off > 0; off >>= 1)
            v += __shfl_down_sync(0xffffffffu, v, off);
        if (lane == 0) out[0] = v;
    }
}

extern "C" void kernel_launch(void* const* d_in, const int* in_sizes, int n_in,
                              void* d_out, int out_size) {
    const float* R            = (const float*)d_in[0];
    const int*   Z            = (const int*)d_in[1];
    const int*   idx          = (const int*)d_in[2];
    const float* a_exp        = (const float*)d_in[3];
    const float* a_num        = (const float*)d_in[4];
    const float* coefficients = (const float*)d_in[5];
    const float* exponents    = (const float*)d_in[6];
    float* out = (float*)d_out;

    int n_atoms = in_sizes[1];
    int n_edges = in_sizes[2] / 2;

    int n_pack_threads = (n_atoms + 3) / 4;
    int pack_grid = (n_pack_threads + PACK_BLK - 1) / PACK_BLK;
    pack_kernel<<<pack_grid, PACK_BLK>>>(R, Z, a_exp, n_atoms);

    int nvec = n_edges >> 2;
    int edge_grid = (nvec + EDGE_BLK - 1) / EDGE_BLK;
    if (edge_grid < 1) edge_grid = 1;
    if (edge_grid > MAX_BLOCKS) edge_grid = MAX_BLOCKS;  // (not hit at E=6.4M)
    edge_kernel<<<edge_grid, EDGE_BLK>>>(idx, n_edges, n_atoms,
                                         a_num, coefficients, exponents);

    final_reduce_kernel<<<1, 1024>>>(out, edge_grid, idx, n_edges, n_atoms,
                                     a_num, coefficients, exponents);
}